// round 1
// baseline (speedup 1.0000x reference)
#include <cuda_runtime.h>

#define HH 128
#define WW 256
#define SS 12
#define CC 32
#define TEMP 7.0f

// Pass-invariant dot table: dot[h][w][x] = sum_c left[c,h,w] * right[c,h,x]
// Only the band x in [w-88, w+8) is ever computed/read.
__device__ float g_tab[HH * WW * WW];           // 33.5 MB
__device__ float g_noiseA[SS * HH * WW];        // ping
__device__ float g_noiseB[SS * HH * WW];        // pong

// ---------------------------------------------------------------------------
// Table build: per (row, half-row) block, register-tiled 8x8 FFMA GEMM over
// the disparity band. A (left) reads are warp-broadcast (lanes share tw),
// B (right) reads are float4 from shared. 192 threads = 16 w-tiles x 12 x-tiles.
// ---------------------------------------------------------------------------
__global__ __launch_bounds__(192) void build_table_kernel(
    const float* __restrict__ left, const float* __restrict__ right) {
    __shared__ float As[CC][128];   // left half-row  [c][w_local]   16 KB
    __shared__ float Rs[CC][WW];    // right full row [c][x]         32 KB

    const int h = blockIdx.y;
    const int wbase = blockIdx.x * 128;
    const int tid = threadIdx.x;

    for (int i = tid; i < CC * 128; i += 192) {
        int c = i >> 7, wl = i & 127;
        As[c][wl] = left[(c * HH + h) * WW + wbase + wl];
    }
    for (int i = tid; i < CC * WW; i += 192) {
        int c = i >> 8, x = i & 255;
        Rs[c][x] = right[(c * HH + h) * WW + x];
    }
    __syncthreads();

    const int tw = tid / 12;            // w-tile within half-row: 0..15
    const int j  = tid % 12;            // band x-tile offset: 0..11
    const int twg = (wbase >> 3) + tw;  // global w-tile 0..31
    const int txg = twg - 10 + j;       // x-tiles [twg-10, twg+1]
    if (txg < 0 || txg > 31) return;

    const int wl = tw * 8;              // local w base
    const int x  = txg * 8;             // global x base

    float acc[8][8];
    #pragma unroll
    for (int i = 0; i < 8; i++)
        #pragma unroll
        for (int q = 0; q < 8; q++) acc[i][q] = 0.0f;

    #pragma unroll 8
    for (int k = 0; k < CC; k++) {
        float a[8], b[8];
        *(float4*)&a[0] = *(const float4*)&As[k][wl];
        *(float4*)&a[4] = *(const float4*)&As[k][wl + 4];
        *(float4*)&b[0] = *(const float4*)&Rs[k][x];
        *(float4*)&b[4] = *(const float4*)&Rs[k][x + 4];
        #pragma unroll
        for (int i = 0; i < 8; i++)
            #pragma unroll
            for (int q = 0; q < 8; q++)
                acc[i][q] += a[i] * b[q];
    }

    float* dst = g_tab + ((size_t)(h * WW + wbase + wl)) * WW + x;
    #pragma unroll
    for (int i = 0; i < 8; i++) {
        float4 s0 = make_float4(acc[i][0], acc[i][1], acc[i][2], acc[i][3]);
        float4 s1 = make_float4(acc[i][4], acc[i][5], acc[i][6], acc[i][7]);
        *(float4*)(dst + (size_t)i * WW)     = s0;
        *(float4*)(dst + (size_t)i * WW + 4) = s1;
    }
}

// ---------------------------------------------------------------------------
// One PatchMatch pass: propagate noise (3 taps H or V), bilinear cost from
// the dot table, softmax over taps, emit new noise + disp.
// grid = (S, H), block = W threads.
// Passes: 0=H,1=V,2=H,3=V.  noise flow: ext->A->B->A->B.
// ---------------------------------------------------------------------------
__global__ __launch_bounds__(WW) void pm_pass_kernel(
    const float* __restrict__ minD, const float* __restrict__ maxD,
    const float* __restrict__ ext_noise, float* __restrict__ disp_out,
    int pass) {
    const int w = threadIdx.x;
    const int h = blockIdx.y;
    const int s = blockIdx.x;
    const int pix = h * WW + w;

    const float* nin = (pass == 0) ? ext_noise
                                   : ((pass & 1) ? g_noiseA : g_noiseB);
    float* nout = (pass & 1) ? g_noiseB : g_noiseA;
    const bool horizontal = ((pass & 1) == 0);

    const float md = fmaxf(minD[pix], 0.0f);
    const float Md = fmaxf(maxD[pix], 0.0f);
    const float search = Md - md;
    const float inv = 1.0f / (float)(SS + 1);
    const float im = md + search * ((float)(s + 1) * inv);

    const float* nsrc = nin + s * HH * WW;
    float np[3];
    if (horizontal) {
        np[0] = (w >= 1)     ? nsrc[pix - 1] : 0.0f;
        np[1] = nsrc[pix];
        np[2] = (w < WW - 1) ? nsrc[pix + 1] : 0.0f;
    } else {
        np[0] = (h >= 1)     ? nsrc[pix - WW] : 0.0f;
        np[1] = nsrc[pix];
        np[2] = (h < HH - 1) ? nsrc[pix + WW] : 0.0f;
    }

    const float* tabrow = g_tab + (size_t)pix * WW;
    float cost[3], dsv[3];
    #pragma unroll
    for (int c = 0; c < 3; c++) {
        float disp = im + np[c] * search * inv;
        dsv[c] = disp;
        float xs = (float)w - disp;
        float x0f = floorf(xs);
        float frac = xs - x0f;
        int x0 = (int)x0f;
        int x1 = x0 + 1;
        // Predicated reads (NOT weight-zeroed) so uninitialized band slots
        // can never inject NaN via 0*garbage.
        float d0 = (x0 >= 0 && x0 < WW) ? tabrow[x0] : 0.0f;
        float d1 = (x1 >= 0 && x1 < WW) ? tabrow[x1] : 0.0f;
        cost[c] = (d0 * (1.0f - frac) + d1 * frac) * (TEMP / (float)CC);
    }

    // softmax over the 3 filter taps (max-subtracted, like jax.nn.softmax)
    float m = fmaxf(cost[0], fmaxf(cost[1], cost[2]));
    float e0 = expf(cost[0] - m);
    float e1 = expf(cost[1] - m);
    float e2 = expf(cost[2] - m);
    float rZ = 1.0f / (e0 + e1 + e2);

    nout[s * HH * WW + pix]     = (e0 * np[0]  + e1 * np[1]  + e2 * np[2])  * rZ;
    disp_out[s * HH * WW + pix] = (e0 * dsv[0] + e1 * dsv[1] + e2 * dsv[2]) * rZ;
}

extern "C" void kernel_launch(void* const* d_in, const int* in_sizes, int n_in,
                              void* d_out, int out_size) {
    const float* left  = (const float*)d_in[0];
    const float* right = (const float*)d_in[1];
    const float* minD  = (const float*)d_in[2];
    const float* maxD  = (const float*)d_in[3];
    const float* noise = (const float*)d_in[4];
    float* disp = (float*)d_out;

    build_table_kernel<<<dim3(2, HH), 192>>>(left, right);
    for (int p = 0; p < 4; p++) {
        pm_pass_kernel<<<dim3(SS, HH), WW>>>(minD, maxD, noise, disp, p);
    }
}